// round 14
// baseline (speedup 1.0000x reference)
#include <cuda_runtime.h>
#include <cuda_bf16.h>
#include <cuda_fp16.h>
#include <math.h>
#include <stdint.h>

#define BB 4
#define SS 2048
#define FF 512
#define HH 8
#define DD 64
#define HD 512
#define MT (BB*SS)   // 8192

// ---------------------------------------------------------------------------
// Scratch (static device globals = sanctioned scratch path)
// ---------------------------------------------------------------------------
__device__ __nv_bfloat16 g_Xh[MT*FF];
__device__ __nv_bfloat16 g_Xl[MT*FF];
__device__ __half        g_X16[MT*FF];     // fp16 X (for V projection)
__device__ __nv_bfloat16 g_Wh[2*HD*FF];    // Wq, Wk hi
__device__ __nv_bfloat16 g_Wl[2*HD*FF];    // Wq, Wk lo
__device__ __half        g_Wv16[HD*FF];    // fp16 Wv
__device__ __nv_bfloat16 g_Qh[BB*HH*SS*DD];   // bf16 hi
__device__ __nv_bfloat16 g_Kh[BB*HH*SS*DD];   // bf16 hi
__device__ int8_t g_Q8 [BB*HH*SS*DD];   // int8 of Q      (scale 127/4)
__device__ int8_t g_Q8r[BB*HH*SS*DD];   // int8 of Q-Qh   (scale 127*128)
__device__ int8_t g_K8 [BB*HH*SS*DD];
__device__ int8_t g_K8r[BB*HH*SS*DD];
__device__ __half g_Vth[BB*HH*DD*SS];   // transposed [b,h,d,s], fp16
__device__ float g_zt[SS];              // zt * log2(e)

// ---------------------------------------------------------------------------
// Helpers
// ---------------------------------------------------------------------------
__device__ __forceinline__ uint32_t smem_u32(const void* p) {
    uint32_t a;
    asm("{ .reg .u64 t; cvta.to.shared.u64 t, %1; cvt.u32.u64 %0, t; }"
        : "=r"(a) : "l"(p));
    return a;
}

#define CP_ASYNC16(dst, src) \
    asm volatile("cp.async.cg.shared.global [%0], [%1], 16;" \
        :: "r"(dst), "l"(src) : "memory")
#define CP_COMMIT() asm volatile("cp.async.commit_group;" ::: "memory")
#define CP_WAIT1()  asm volatile("cp.async.wait_group 1;" ::: "memory")

__device__ __forceinline__ void mma_bf16(float* d, const uint32_t* a, const uint32_t* b) {
    asm volatile(
        "mma.sync.aligned.m16n8k16.row.col.f32.bf16.bf16.f32 "
        "{%0,%1,%2,%3}, {%4,%5,%6,%7}, {%8,%9}, {%0,%1,%2,%3};"
        : "+f"(d[0]), "+f"(d[1]), "+f"(d[2]), "+f"(d[3])
        : "r"(a[0]), "r"(a[1]), "r"(a[2]), "r"(a[3]), "r"(b[0]), "r"(b[1]));
}

__device__ __forceinline__ void mma_fp16(float* d, const uint32_t* a, const uint32_t* b) {
    asm volatile(
        "mma.sync.aligned.m16n8k16.row.col.f32.f16.f16.f32 "
        "{%0,%1,%2,%3}, {%4,%5,%6,%7}, {%8,%9}, {%0,%1,%2,%3};"
        : "+f"(d[0]), "+f"(d[1]), "+f"(d[2]), "+f"(d[3])
        : "r"(a[0]), "r"(a[1]), "r"(a[2]), "r"(a[3]), "r"(b[0]), "r"(b[1]));
}

// int8 MMA, k=32, s32 accumulate (sm_80+)
__device__ __forceinline__ void mma_s8(int* d, const uint32_t* a, const uint32_t* b) {
    asm volatile(
        "mma.sync.aligned.m16n8k32.row.col.s32.s8.s8.s32 "
        "{%0,%1,%2,%3}, {%4,%5,%6,%7}, {%8,%9}, {%0,%1,%2,%3};"
        : "+r"(d[0]), "+r"(d[1]), "+r"(d[2]), "+r"(d[3])
        : "r"(a[0]), "r"(a[1]), "r"(a[2]), "r"(a[3]), "r"(b[0]), "r"(b[1]));
}

__device__ __forceinline__ void ldsm4(uint32_t* r, uint32_t addr) {
    asm volatile("ldmatrix.sync.aligned.m8n8.x4.shared.b16 {%0,%1,%2,%3}, [%4];"
        : "=r"(r[0]), "=r"(r[1]), "=r"(r[2]), "=r"(r[3]) : "r"(addr));
}

__device__ __forceinline__ uint32_t pk2(__nv_bfloat16 a, __nv_bfloat16 b) {
    return (uint32_t)__bfloat16_as_ushort(a) | ((uint32_t)__bfloat16_as_ushort(b) << 16);
}

__device__ __forceinline__ uint32_t pk2h(__half a, __half b) {
    return (uint32_t)__half_as_ushort(a) | ((uint32_t)__half_as_ushort(b) << 16);
}

__device__ __forceinline__ float ex2f(float x) {
    float y;
    asm("ex2.approx.f32 %0, %1;" : "=f"(y) : "f"(x));
    return y;
}

__device__ __forceinline__ uint32_t cvt_f16x2(float hi, float lo) {
    uint32_t d;
    asm("cvt.rn.f16x2.f32 %0, %1, %2;" : "=r"(d) : "f"(hi), "f"(lo));
    return d;
}

__device__ __forceinline__ int q8clamp(float x) {
    int i = __float2int_rn(x);
    return max(-127, min(127, i));
}

// ---------------------------------------------------------------------------
// z_hat table (log2-domain: includes 1/sqrt(D) and log2(e))
// ---------------------------------------------------------------------------
__global__ void zhat_kernel(const float* __restrict__ ah, const float* __restrict__ vh)
{
    int i = blockIdx.x * blockDim.x + threadIdx.x;
    if (i < SS) {
        float a = ah[0], v = vh[0];
        float z = 1.0f + expf(v) / (1.0f + expf(v - a * (float)i));
        g_zt[i] = z * 0.125f * 1.4426950408889634f;
    }
}

// ---------------------------------------------------------------------------
// Split: X -> bf16 hi/lo + fp16; Wq/Wk -> bf16 hi/lo; Wv -> fp16.
// ---------------------------------------------------------------------------
#define NX8 (MT*FF/8)
#define NW8_1 (HD*FF/8)

__global__ __launch_bounds__(256) void split_kernel(
    const float* __restrict__ X, const float* __restrict__ Wq,
    const float* __restrict__ Wk, const float* __restrict__ Wv)
{
    int i = blockIdx.x * 256 + threadIdx.x;
    if (i < NX8) {
        int off = i;
        float4 v0 = ((const float4*)X)[(size_t)off * 2];
        float4 v1 = ((const float4*)X)[(size_t)off * 2 + 1];
        float f[8] = {v0.x, v0.y, v0.z, v0.w, v1.x, v1.y, v1.z, v1.w};
        __nv_bfloat16 h[8], l[8];
        __half p[8];
#pragma unroll
        for (int k = 0; k < 8; k++) {
            h[k] = __float2bfloat16(f[k]);
            l[k] = __float2bfloat16(f[k] - __bfloat162float(h[k]));
            p[k] = __float2half_rn(f[k]);
        }
        uint4 H, L, P;
        H.x = pk2(h[0], h[1]); H.y = pk2(h[2], h[3]);
        H.z = pk2(h[4], h[5]); H.w = pk2(h[6], h[7]);
        L.x = pk2(l[0], l[1]); L.y = pk2(l[2], l[3]);
        L.z = pk2(l[4], l[5]); L.w = pk2(l[6], l[7]);
        P.x = pk2h(p[0], p[1]); P.y = pk2h(p[2], p[3]);
        P.z = pk2h(p[4], p[5]); P.w = pk2h(p[6], p[7]);
        ((uint4*)g_Xh)[off] = H;
        ((uint4*)g_Xl)[off] = L;
        ((uint4*)g_X16)[off] = P;
    } else {
        int j = i - NX8;
        int m = j >> 15;           // 0=Wq, 1=Wk, 2=Wv
        int off = j & 32767;
        const float* src = (m == 0) ? Wq : ((m == 1) ? Wk : Wv);
        float4 v0 = ((const float4*)src)[(size_t)off * 2];
        float4 v1 = ((const float4*)src)[(size_t)off * 2 + 1];
        float f[8] = {v0.x, v0.y, v0.z, v0.w, v1.x, v1.y, v1.z, v1.w};
        if (m < 2) {
            __nv_bfloat16 h[8], l[8];
#pragma unroll
            for (int k = 0; k < 8; k++) {
                h[k] = __float2bfloat16(f[k]);
                l[k] = __float2bfloat16(f[k] - __bfloat162float(h[k]));
            }
            uint4 H, L;
            H.x = pk2(h[0], h[1]); H.y = pk2(h[2], h[3]);
            H.z = pk2(h[4], h[5]); H.w = pk2(h[6], h[7]);
            L.x = pk2(l[0], l[1]); L.y = pk2(l[2], l[3]);
            L.z = pk2(l[4], l[5]); L.w = pk2(l[6], l[7]);
            size_t o = (size_t)m * NW8_1 + off;
            ((uint4*)g_Wh)[o] = H;
            ((uint4*)g_Wl)[o] = L;
        } else {
            __half p[8];
#pragma unroll
            for (int k = 0; k < 8; k++) p[k] = __float2half_rn(f[k]);
            uint4 P;
            P.x = pk2h(p[0], p[1]); P.y = pk2h(p[2], p[3]);
            P.z = pk2h(p[4], p[5]); P.w = pk2h(p[6], p[7]);
            ((uint4*)g_Wv16)[off] = P;
        }
    }
}

// ---------------------------------------------------------------------------
// Fused QKV projection. nb<8: Q/K via bf16x3. nb>=8: V via single fp16 MMA.
// Q/K epilogue -> bf16 hi + int8 (y, residual) [b,h,s,d]; V -> fp16 [b,h,d,s].
// ---------------------------------------------------------------------------
#define PROW 144
#define PARR 18432
#define PSTG (4*PARR)
#define PROJ_SMEM (2*PSTG)

__global__ __launch_bounds__(256) void proj_mma(
    const float* __restrict__ bq, const float* __restrict__ bk,
    const float* __restrict__ bv)
{
    extern __shared__ char sm[];
    const uint32_t sbase = smem_u32(sm);
    const int tid = threadIdx.x;
    const int w = tid >> 5, lane = tid & 31;
    const int gr = lane >> 2, qt = lane & 3;
    const int nb = blockIdx.x;          // 0..11
    const int m0 = blockIdx.y * 128;

    const uint32_t rowoffB = (uint32_t)(((lane & 7) + ((lane >> 4) << 3)) * PROW
                                        + ((lane >> 3) & 1) * 16);
    const uint32_t rowoffA = (uint32_t)(((lane & 7) + (((lane >> 3) & 1) << 3)) * PROW
                                        + (lane >> 4) * 16);

    float acc[16][4];
#pragma unroll
    for (int i = 0; i < 16; i++)
#pragma unroll
        for (int j = 0; j < 4; j++) acc[i][j] = 0.f;

    const uint32_t w16off = (uint32_t)(w * 16 * PROW);

    if (nb < 8) {
        auto fill = [&](int stg, int k0) {
            char* dstb = sm + stg * PSTG;
#pragma unroll
            for (int ii = 0; ii < 16; ii++) {
                int idx = ii * 256 + tid;
                int arr = idx >> 10;
                int r = (idx >> 3) & 127;
                int c = idx & 7;
                const __nv_bfloat16* src;
                if (arr == 0)      src = g_Xh + (size_t)(m0 + r) * FF + k0 + c * 8;
                else if (arr == 1) src = g_Xl + (size_t)(m0 + r) * FF + k0 + c * 8;
                else if (arr == 2) src = g_Wh + (size_t)(nb * 128 + r) * FF + k0 + c * 8;
                else               src = g_Wl + (size_t)(nb * 128 + r) * FF + k0 + c * 8;
                uint32_t d = smem_u32(dstb + arr * PARR + r * PROW + c * 16);
                CP_ASYNC16(d, src);
            }
            CP_COMMIT();
        };

        fill(0, 0);
        fill(1, 64);

#pragma unroll 1
        for (int ks = 0; ks < 8; ks++) {
            CP_WAIT1();
            __syncthreads();
            const uint32_t B   = sbase + (ks & 1) * PSTG;
            const uint32_t aXh = B;
            const uint32_t aXl = B + PARR;
            const uint32_t aWh = B + 2 * PARR;
            const uint32_t aWl = B + 3 * PARR;
#pragma unroll
            for (int kf = 0; kf < 4; kf++) {
                uint32_t xh[4], xl[4];
                ldsm4(xh, aXh + w16off + kf * 32 + rowoffA);
                ldsm4(xl, aXl + w16off + kf * 32 + rowoffA);
#pragma unroll
                for (int np = 0; np < 4; np++) {
                    uint32_t wh0[4], wl0[4], wh1[4], wl1[4];
                    ldsm4(wh0, aWh + (2 * np) * (16 * PROW) + kf * 32 + rowoffB);
                    ldsm4(wl0, aWl + (2 * np) * (16 * PROW) + kf * 32 + rowoffB);
                    ldsm4(wh1, aWh + (2 * np + 1) * (16 * PROW) + kf * 32 + rowoffB);
                    ldsm4(wl1, aWl + (2 * np + 1) * (16 * PROW) + kf * 32 + rowoffB);
                    float* a0 = acc[4 * np];
                    float* a1 = acc[4 * np + 1];
                    float* a2 = acc[4 * np + 2];
                    float* a3 = acc[4 * np + 3];
                    mma_bf16(a0, xh, &wh0[0]); mma_bf16(a1, xh, &wh0[2]);
                    mma_bf16(a2, xh, &wh1[0]); mma_bf16(a3, xh, &wh1[2]);
                    mma_bf16(a0, xh, &wl0[0]); mma_bf16(a1, xh, &wl0[2]);
                    mma_bf16(a2, xh, &wl1[0]); mma_bf16(a3, xh, &wl1[2]);
                    mma_bf16(a0, xl, &wh0[0]); mma_bf16(a1, xl, &wh0[2]);
                    mma_bf16(a2, xl, &wh1[0]); mma_bf16(a3, xl, &wh1[2]);
                }
            }
            __syncthreads();
            if (ks + 2 < 8) fill(ks & 1, (ks + 2) * 64);
        }
    } else {
        auto fillv = [&](int stg, int k0) {
            char* dstb = sm + stg * PSTG;
#pragma unroll
            for (int ii = 0; ii < 8; ii++) {
                int idx = ii * 256 + tid;
                int arr = idx >> 10;            // 0: X16, 1: Wv16
                int r = (idx >> 3) & 127;
                int c = idx & 7;
                const __half* src = (arr == 0)
                    ? g_X16 + (size_t)(m0 + r) * FF + k0 + c * 8
                    : g_Wv16 + (size_t)((nb - 8) * 128 + r) * FF + k0 + c * 8;
                uint32_t d = smem_u32(dstb + arr * PARR + r * PROW + c * 16);
                CP_ASYNC16(d, src);
            }
            CP_COMMIT();
        };

        fillv(0, 0);
        fillv(1, 64);

#pragma unroll 1
        for (int ks = 0; ks < 8; ks++) {
            CP_WAIT1();
            __syncthreads();
            const uint32_t B   = sbase + (ks & 1) * PSTG;
            const uint32_t aX  = B;
            const uint32_t aWv = B + PARR;
#pragma unroll
            for (int kf = 0; kf < 4; kf++) {
                uint32_t x16[4];
                ldsm4(x16, aX + w16off + kf * 32 + rowoffA);
#pragma unroll
                for (int np = 0; np < 4; np++) {
                    uint32_t wv0[4], wv1[4];
                    ldsm4(wv0, aWv + (2 * np) * (16 * PROW) + kf * 32 + rowoffB);
                    ldsm4(wv1, aWv + (2 * np + 1) * (16 * PROW) + kf * 32 + rowoffB);
                    mma_fp16(acc[4 * np],     x16, &wv0[0]);
                    mma_fp16(acc[4 * np + 1], x16, &wv0[2]);
                    mma_fp16(acc[4 * np + 2], x16, &wv1[0]);
                    mma_fp16(acc[4 * np + 3], x16, &wv1[2]);
                }
            }
            __syncthreads();
            if (ks + 2 < 8) fillv(ks & 1, (ks + 2) * 64);
        }
    }

    // ---- epilogue ----
    const int r0 = m0 + w * 16 + gr;
#pragma unroll
    for (int nf = 0; nf < 16; nf++) {
        int ng;
        {
            int np = nf >> 2, j = nf & 3;
            int nfp = 2 * np + (j >> 1);
            int oldnf = 2 * nfp + (j & 1);
            ng = nb * 128 + oldnf * 8 + qt * 2;
        }
        int sel = ng >> 9;
        int within = ng & 511;
        const float* bias = (sel == 0) ? bq : (sel == 1) ? bk : bv;
        float b0 = bias[within], b1 = bias[within + 1];
        int h = within >> 6, d = within & 63;
#pragma unroll
        for (int half = 0; half < 2; half++) {
            int m = r0 + half * 8;
            int bb = m >> 11, s = m & 2047;
            float y0 = acc[nf][half * 2 + 0] + b0;
            float y1 = acc[nf][half * 2 + 1] + b1;
            if (sel < 2) {
                __nv_bfloat16 h0 = __float2bfloat16(y0);
                __nv_bfloat16 h1 = __float2bfloat16(y1);
                float res0 = y0 - __bfloat162float(h0);
                float res1 = y1 - __bfloat162float(h1);
                int i0 = q8clamp(y0 * 31.75f);
                int i1 = q8clamp(y1 * 31.75f);
                int j0 = q8clamp(res0 * 16256.0f);
                int j1 = q8clamp(res1 * 16256.0f);
                __nv_bfloat16* dh = (sel == 0) ? g_Qh : g_Kh;
                int8_t* d8  = (sel == 0) ? g_Q8  : g_K8;
                int8_t* d8r = (sel == 0) ? g_Q8r : g_K8r;
                size_t a = (((size_t)(bb * HH + h)) * SS + s) * DD + d;
                *(uint32_t*)&dh[a] = pk2(h0, h1);
                *(unsigned short*)&d8[a]  = (unsigned short)((i0 & 0xff) | ((i1 & 0xff) << 8));
                *(unsigned short*)&d8r[a] = (unsigned short)((j0 & 0xff) | ((j1 & 0xff) << 8));
            } else {
                size_t a0 = (((size_t)(bb * HH + h)) * DD + d) * SS + s;
                g_Vth[a0]      = __float2half_rn(y0);
                g_Vth[a0 + SS] = __float2half_rn(y1);
            }
        }
    }
}

// ---------------------------------------------------------------------------
// Flash attention: S = Qh·Kh (bf16) + int8 cross (k32), PV = fp16.
// 128 threads (4 warps, 64 q-rows), 32-key tiles, 2-stage ring, 4 CTAs/SM.
// ---------------------------------------------------------------------------
#define NT 64
#define KROW 144
#define K8ROW 80               // 64 data + 16 pad (conflict-free ldsm)
#define VROW 80
#define KARR (32*KROW)         // 4608
#define K8ARR (32*K8ROW)       // 2560
#define VARR (64*VROW)         // 5120
#define OK8  KARR              // K8 offset within stage
#define OK8R (KARR + K8ARR)
#define OV   (KARR + 2*K8ARR)
#define ASTG (KARR + 2*K8ARR + VARR)   // 14848
#define AZT  (2*ASTG)                  // 29696
#define ATTN_SMEM (AZT + SS*4)         // 37888

__global__ __launch_bounds__(128, 4) void attn_mma(float* __restrict__ out)
{
    extern __shared__ char sm[];
    const uint32_t sbase = smem_u32(sm);
    float* zts = (float*)(sm + AZT);
    const int tid = threadIdx.x;
    const int w = tid >> 5, lane = tid & 31;
    const int gr = lane >> 2, qt = lane & 3;
    const int bh = blockIdx.y;
    const int q0 = blockIdx.x * 64;

    const uint32_t rowK = (uint32_t)(((lane & 7) + ((lane >> 4) << 3)) * KROW
                                     + ((lane >> 3) & 1) * 16);
    const uint32_t rowI8 = (uint32_t)(((lane & 7) + ((lane >> 4) << 3)) * K8ROW
                                      + ((lane >> 3) & 1) * 16);
    const uint32_t rowV = (uint32_t)(((lane & 7) + ((lane >> 4) << 3)) * VROW
                                     + ((lane >> 3) & 1) * 16);

    for (int i = tid; i < SS; i += 128) zts[i] = g_zt[i];

    const int r0 = q0 + w * 16 + gr;
    // Qh bf16 fragments
    const __nv_bfloat16* Qh = g_Qh + (size_t)bh * SS * DD;
    uint32_t qah[4][4];
#pragma unroll
    for (int kf = 0; kf < 4; kf++) {
        int col = kf * 16 + qt * 2;
        qah[kf][0] = *(const uint32_t*)(Qh + (size_t)r0 * 64 + col);
        qah[kf][1] = *(const uint32_t*)(Qh + (size_t)(r0 + 8) * 64 + col);
        qah[kf][2] = *(const uint32_t*)(Qh + (size_t)r0 * 64 + col + 8);
        qah[kf][3] = *(const uint32_t*)(Qh + (size_t)(r0 + 8) * 64 + col + 8);
    }
    // int8 Q fragments (k32 layout): a0=row r0 k=qt*4, a1=r0+8, a2=+16, a3=r0+8,+16
    const int8_t* Q8  = g_Q8  + (size_t)bh * SS * DD;
    const int8_t* Q8r = g_Q8r + (size_t)bh * SS * DD;
    uint32_t q8[2][4], q8r[2][4];
#pragma unroll
    for (int kc = 0; kc < 2; kc++) {
        int col = kc * 32 + qt * 4;
        q8[kc][0]  = *(const uint32_t*)(Q8  + (size_t)r0 * 64 + col);
        q8[kc][1]  = *(const uint32_t*)(Q8  + (size_t)(r0 + 8) * 64 + col);
        q8[kc][2]  = *(const uint32_t*)(Q8  + (size_t)r0 * 64 + col + 16);
        q8[kc][3]  = *(const uint32_t*)(Q8  + (size_t)(r0 + 8) * 64 + col + 16);
        q8r[kc][0] = *(const uint32_t*)(Q8r + (size_t)r0 * 64 + col);
        q8r[kc][1] = *(const uint32_t*)(Q8r + (size_t)(r0 + 8) * 64 + col);
        q8r[kc][2] = *(const uint32_t*)(Q8r + (size_t)r0 * 64 + col + 16);
        q8r[kc][3] = *(const uint32_t*)(Q8r + (size_t)(r0 + 8) * 64 + col + 16);
    }

    auto fill = [&](int slot, int k0) {
        char* dstb = sm + slot * ASTG;
#pragma unroll
        for (int ii = 0; ii < 6; ii++) {
            int idx = ii * 128 + tid;       // 0..767
            uint32_t d;
            if (idx < 256) {                // Kh bf16: 32 rows x 128B
                int r = idx >> 3, c = idx & 7;
                const __nv_bfloat16* src =
                    g_Kh + ((size_t)bh * SS + k0 + r) * 64 + c * 8;
                d = smem_u32(dstb + r * KROW + c * 16);
                CP_ASYNC16(d, src);
            } else if (idx < 384) {         // K8: 32 rows x 64B
                int j = idx - 256;
                int r = j >> 2, c = j & 3;
                const int8_t* src = g_K8 + ((size_t)bh * SS + k0 + r) * 64 + c * 16;
                d = smem_u32(dstb + OK8 + r * K8ROW + c * 16);
                CP_ASYNC16(d, src);
            } else if (idx < 512) {         // K8r
                int j = idx - 384;
                int r = j >> 2, c = j & 3;
                const int8_t* src = g_K8r + ((size_t)bh * SS + k0 + r) * 64 + c * 16;
                d = smem_u32(dstb + OK8R + r * K8ROW + c * 16);
                CP_ASYNC16(d, src);
            } else {                        // V fp16: 64 rows x 64B
                int j = idx - 512;
                int r = j >> 2, c = j & 3;
                const __half* src = g_Vth + ((size_t)bh * DD + r) * SS + k0 + c * 8;
                d = smem_u32(dstb + OV + r * VROW + c * 16);
                CP_ASYNC16(d, src);
            }
        }
        CP_COMMIT();
    };

    fill(0, 0);
    fill(1, 32);

    float O[8][4];
#pragma unroll
    for (int i = 0; i < 8; i++)
#pragma unroll
        for (int j = 0; j < 4; j++) O[i][j] = 0.f;
    float m0r = -1e30f, m1r = -1e30f, l0r = 0.f, l1r = 0.f;

    const float DQ = 4.0f / (127.0f * 127.0f * 128.0f);

#pragma unroll 1
    for (int kt = 0; kt < NT; kt++) {
        CP_WAIT1();
        __syncthreads();
        const uint32_t B    = sbase + (kt & 1) * ASTG;
        const uint32_t aKh  = B;
        const uint32_t aK8  = B + OK8;
        const uint32_t aK8r = B + OK8R;
        const uint32_t aVth = B + OV;
        const int k0 = kt * 32;

        // ---- S main term: Qh·Kh (bf16), acc-major ----
        float S[4][4];
#pragma unroll
        for (int i = 0; i < 4; i++)
#pragma unroll
            for (int j = 0; j < 4; j++) S[i][j] = 0.f;

#pragma unroll
        for (int kf = 0; kf < 4; kf++) {
            uint32_t rh0[4], rh1[4];
            ldsm4(rh0, aKh + kf * 32 + rowK);
            ldsm4(rh1, aKh + 16 * KROW + kf * 32 + rowK);
            mma_bf16(S[0], qah[kf], &rh0[0]); mma_bf16(S[1], qah[kf], &rh0[2]);
            mma_bf16(S[2], qah[kf], &rh1[0]); mma_bf16(S[3], qah[kf], &rh1[2]);
        }

        // ---- S cross terms: int8 k32, shared s32 accumulator ----
        int ia[4][4];
#pragma unroll
        for (int i = 0; i < 4; i++)
#pragma unroll
            for (int j = 0; j < 4; j++) ia[i][j] = 0;

#pragma unroll
        for (int kc = 0; kc < 2; kc++) {
            uint32_t kh8a[4], kh8b[4], kr8a[4], kr8b[4];
            ldsm4(kr8a, aK8r + kc * 32 + rowI8);                 // keys 0-15
            ldsm4(kr8b, aK8r + 16 * K8ROW + kc * 32 + rowI8);    // keys 16-31
            ldsm4(kh8a, aK8 + kc * 32 + rowI8);
            ldsm4(kh8b, aK8 + 16 * K8ROW + kc * 32 + rowI8);
            // Q8 · K8r
            mma_s8(ia[0], q8[kc], &kr8a[0]); mma_s8(ia[1], q8[kc], &kr8a[2]);
            mma_s8(ia[2], q8[kc], &kr8b[0]); mma_s8(ia[3], q8[kc], &kr8b[2]);
            // Q8r · K8
            mma_s8(ia[0], q8r[kc], &kh8a[0]); mma_s8(ia[1], q8r[kc], &kh8a[2]);
            mma_s8(ia[2], q8r[kc], &kh8b[0]); mma_s8(ia[3], q8r[kc], &kh8b[2]);
        }
#pragma unroll
        for (int i = 0; i < 4; i++)
#pragma unroll
            for (int j = 0; j < 4; j++)
                S[i][j] = fmaf((float)ia[i][j], DQ, S[i][j]);

        // ---- bias + online softmax (log2 domain, lazy rescale) ----
        float mt0 = -1e30f, mt1 = -1e30f;
#pragma unroll
        for (int nf = 0; nf < 4; nf++) {
            int c0 = k0 + nf * 8 + qt * 2;
            S[nf][0] *= zts[abs(r0 - c0)];
            S[nf][1] *= zts[abs(r0 - c0 - 1)];
            S[nf][2] *= zts[abs(r0 + 8 - c0)];
            S[nf][3] *= zts[abs(r0 + 8 - c0 - 1)];
            mt0 = fmaxf(mt0, fmaxf(S[nf][0], S[nf][1]));
            mt1 = fmaxf(mt1, fmaxf(S[nf][2], S[nf][3]));
        }
        mt0 = fmaxf(mt0, __shfl_xor_sync(0xffffffffu, mt0, 1));
        mt0 = fmaxf(mt0, __shfl_xor_sync(0xffffffffu, mt0, 2));
        mt1 = fmaxf(mt1, __shfl_xor_sync(0xffffffffu, mt1, 1));
        mt1 = fmaxf(mt1, __shfl_xor_sync(0xffffffffu, mt1, 2));
        bool changed = (mt0 > m0r) || (mt1 > m1r);
        if (__any_sync(0xffffffffu, changed)) {
            float mn0 = fmaxf(m0r, mt0), mn1 = fmaxf(m1r, mt1);
            float a0 = ex2f(m0r - mn0), a1 = ex2f(m1r - mn1);
            m0r = mn0; m1r = mn1;
            l0r *= a0; l1r *= a1;
#pragma unroll
            for (int nf = 0; nf < 8; nf++) {
                O[nf][0] *= a0; O[nf][1] *= a0;
                O[nf][2] *= a1; O[nf][3] *= a1;
            }
        }

        float s0 = 0.f, s1 = 0.f;
        uint32_t ph[2][4];
#pragma unroll
        for (int nf = 0; nf < 4; nf++) {
            float e0 = ex2f(S[nf][0] - m0r);
            float e1 = ex2f(S[nf][1] - m0r);
            float e2 = ex2f(S[nf][2] - m1r);
            float e3 = ex2f(S[nf][3] - m1r);
            s0 += e0 + e1; s1 += e2 + e3;
            uint32_t p01 = cvt_f16x2(e1, e0);
            uint32_t p23 = cvt_f16x2(e3, e2);
            int kf = nf >> 1;
            if ((nf & 1) == 0) { ph[kf][0] = p01; ph[kf][1] = p23; }
            else               { ph[kf][2] = p01; ph[kf][3] = p23; }
        }
        l0r += s0;
        l1r += s1;

        // ---- O += P V (fp16, 1 term), acc-major order ----
#pragma unroll
        for (int kf = 0; kf < 2; kf++) {
#pragma unroll
            for (int g = 0; g < 2; g++) {
                uint32_t va0[4], va1[4];
                ldsm4(va0, aVth + (2 * g) * (16 * VROW) + kf * 32 + rowV);
                ldsm4(va1, aVth + (2 * g + 1) * (16 * VROW) + kf * 32 + rowV);
                float* o0 = O[4 * g];
                float* o1 = O[4 * g + 1];
                float* o2 = O[4 * g + 2];
                float* o3 = O[4 * g + 3];
                mma_fp16(o0, ph[kf], &va0[0]); mma_fp16(o1, ph[kf], &va0[2]);
                mma_fp16(o2, ph[kf], &va1[0]); mma_fp16(o3, ph[kf], &va1[2]);
            }
        }

        __syncthreads();
        if (kt + 2 < NT) fill(kt & 1, (kt + 2) * 32);
    }

    // ---- epilogue: quad-reduce l, normalize, store ----
    l0r += __shfl_xor_sync(0xffffffffu, l0r, 1);
    l0r += __shfl_xor_sync(0xffffffffu, l0r, 2);
    l1r += __shfl_xor_sync(0xffffffffu, l1r, 1);
    l1r += __shfl_xor_sync(0xffffffffu, l1r, 2);
    float inv0 = 1.0f / l0r, inv1 = 1.0f / l1r;
    int b = bh >> 3, h = bh & 7;
#pragma unroll
    for (int nf = 0; nf < 8; nf++) {
        int g = nf >> 2, j = nf & 3;
        int oldnf = 2 * (2 * g + (j >> 1)) + (j & 1);
        int d = oldnf * 8 + qt * 2;
        float2 o0 = make_float2(O[nf][0] * inv0, O[nf][1] * inv0);
        float2 o1 = make_float2(O[nf][2] * inv1, O[nf][3] * inv1);
        *(float2*)&out[((size_t)(b * SS) + r0) * HD + h * 64 + d]       = o0;
        *(float2*)&out[((size_t)(b * SS) + r0 + 8) * HD + h * 64 + d]   = o1;
    }
}

// ---------------------------------------------------------------------------
extern "C" void kernel_launch(void* const* d_in, const int* in_sizes, int n_in,
                              void* d_out, int out_size)
{
    const float* x  = (const float*)d_in[0];
    const float* Wq = (const float*)d_in[1];
    const float* bq = (const float*)d_in[2];
    const float* Wk = (const float*)d_in[3];
    const float* bk = (const float*)d_in[4];
    const float* Wv = (const float*)d_in[5];
    const float* bv = (const float*)d_in[6];
    const float* ah = (const float*)d_in[7];
    const float* vh = (const float*)d_in[8];
    float* out = (float*)d_out;

    zhat_kernel<<<SS / 256, 256>>>(ah, vh);
    split_kernel<<<(NX8 + 3 * NW8_1) / 256, 256>>>(x, Wq, Wk, Wv);

    cudaFuncSetAttribute(proj_mma,
                         cudaFuncAttributeMaxDynamicSharedMemorySize, PROJ_SMEM);
    proj_mma<<<dim3(12, 64), 256, PROJ_SMEM>>>(bq, bk, bv);

    cudaFuncSetAttribute(attn_mma,
                         cudaFuncAttributeMaxDynamicSharedMemorySize, ATTN_SMEM);
    attn_mma<<<dim3(SS / 64, BB * HH), 128, ATTN_SMEM>>>(out);
}

// round 16
// speedup vs baseline: 1.0136x; 1.0136x over previous
#include <cuda_runtime.h>
#include <cuda_bf16.h>
#include <cuda_fp16.h>
#include <math.h>
#include <stdint.h>

#define BB 4
#define SS 2048
#define FF 512
#define HH 8
#define DD 64
#define HD 512
#define MT (BB*SS)   // 8192

// ---------------------------------------------------------------------------
// Scratch (static device globals = sanctioned scratch path)
// ---------------------------------------------------------------------------
__device__ __nv_bfloat16 g_Xh[MT*FF];
__device__ __half        g_X16[MT*FF];     // fp16 X (for V projection)
__device__ int8_t        g_X8 [MT*FF];     // int8 X        (scale 31.75)
__device__ int8_t        g_X8r[MT*FF];     // int8 X-bf16(X) (scale 16256)
__device__ __nv_bfloat16 g_Wh[2*HD*FF];    // Wq, Wk hi
__device__ int8_t        g_W8 [2*HD*FF];   // int8 W         (scale 512)
__device__ int8_t        g_W8r[2*HD*FF];   // int8 W residual (scale 262144)
__device__ __half        g_Wv16[HD*FF];    // fp16 Wv
__device__ __nv_bfloat16 g_Qh[BB*HH*SS*DD];   // bf16 hi
__device__ __nv_bfloat16 g_Kh[BB*HH*SS*DD];   // bf16 hi
__device__ int8_t g_Q8 [BB*HH*SS*DD];   // int8 of Q      (scale 31.75)
__device__ int8_t g_Q8r[BB*HH*SS*DD];   // int8 of Q-Qh   (scale 16256)
__device__ int8_t g_K8 [BB*HH*SS*DD];
__device__ int8_t g_K8r[BB*HH*SS*DD];
__device__ __half g_Vth[BB*HH*DD*SS];   // transposed [b,h,d,s], fp16
__device__ float g_zt[SS];              // zt * log2(e)

// ---------------------------------------------------------------------------
// Helpers
// ---------------------------------------------------------------------------
__device__ __forceinline__ uint32_t smem_u32(const void* p) {
    uint32_t a;
    asm("{ .reg .u64 t; cvta.to.shared.u64 t, %1; cvt.u32.u64 %0, t; }"
        : "=r"(a) : "l"(p));
    return a;
}

#define CP_ASYNC16(dst, src) \
    asm volatile("cp.async.cg.shared.global [%0], [%1], 16;" \
        :: "r"(dst), "l"(src) : "memory")
#define CP_COMMIT() asm volatile("cp.async.commit_group;" ::: "memory")
#define CP_WAIT1()  asm volatile("cp.async.wait_group 1;" ::: "memory")

__device__ __forceinline__ void mma_bf16(float* d, const uint32_t* a, const uint32_t* b) {
    asm volatile(
        "mma.sync.aligned.m16n8k16.row.col.f32.bf16.bf16.f32 "
        "{%0,%1,%2,%3}, {%4,%5,%6,%7}, {%8,%9}, {%0,%1,%2,%3};"
        : "+f"(d[0]), "+f"(d[1]), "+f"(d[2]), "+f"(d[3])
        : "r"(a[0]), "r"(a[1]), "r"(a[2]), "r"(a[3]), "r"(b[0]), "r"(b[1]));
}

__device__ __forceinline__ void mma_fp16(float* d, const uint32_t* a, const uint32_t* b) {
    asm volatile(
        "mma.sync.aligned.m16n8k16.row.col.f32.f16.f16.f32 "
        "{%0,%1,%2,%3}, {%4,%5,%6,%7}, {%8,%9}, {%0,%1,%2,%3};"
        : "+f"(d[0]), "+f"(d[1]), "+f"(d[2]), "+f"(d[3])
        : "r"(a[0]), "r"(a[1]), "r"(a[2]), "r"(a[3]), "r"(b[0]), "r"(b[1]));
}

// int8 MMA, k=32, s32 accumulate (sm_80+)
__device__ __forceinline__ void mma_s8(int* d, const uint32_t* a, const uint32_t* b) {
    asm volatile(
        "mma.sync.aligned.m16n8k32.row.col.s32.s8.s8.s32 "
        "{%0,%1,%2,%3}, {%4,%5,%6,%7}, {%8,%9}, {%0,%1,%2,%3};"
        : "+r"(d[0]), "+r"(d[1]), "+r"(d[2]), "+r"(d[3])
        : "r"(a[0]), "r"(a[1]), "r"(a[2]), "r"(a[3]), "r"(b[0]), "r"(b[1]));
}

__device__ __forceinline__ void ldsm4(uint32_t* r, uint32_t addr) {
    asm volatile("ldmatrix.sync.aligned.m8n8.x4.shared.b16 {%0,%1,%2,%3}, [%4];"
        : "=r"(r[0]), "=r"(r[1]), "=r"(r[2]), "=r"(r[3]) : "r"(addr));
}

__device__ __forceinline__ uint32_t pk2(__nv_bfloat16 a, __nv_bfloat16 b) {
    return (uint32_t)__bfloat16_as_ushort(a) | ((uint32_t)__bfloat16_as_ushort(b) << 16);
}

__device__ __forceinline__ uint32_t pk2h(__half a, __half b) {
    return (uint32_t)__half_as_ushort(a) | ((uint32_t)__half_as_ushort(b) << 16);
}

__device__ __forceinline__ float ex2f(float x) {
    float y;
    asm("ex2.approx.f32 %0, %1;" : "=f"(y) : "f"(x));
    return y;
}

__device__ __forceinline__ uint32_t cvt_f16x2(float hi, float lo) {
    uint32_t d;
    asm("cvt.rn.f16x2.f32 %0, %1, %2;" : "=r"(d) : "f"(hi), "f"(lo));
    return d;
}

__device__ __forceinline__ int q8clamp(float x) {
    int i = __float2int_rn(x);
    return max(-127, min(127, i));
}

__device__ __forceinline__ uint32_t pk4b(int a, int b, int c, int d) {
    return (uint32_t)(a & 0xff) | ((uint32_t)(b & 0xff) << 8)
         | ((uint32_t)(c & 0xff) << 16) | ((uint32_t)(d & 0xff) << 24);
}

// ---------------------------------------------------------------------------
// z_hat table (log2-domain: includes 1/sqrt(D) and log2(e))
// ---------------------------------------------------------------------------
__global__ void zhat_kernel(const float* __restrict__ ah, const float* __restrict__ vh)
{
    int i = blockIdx.x * blockDim.x + threadIdx.x;
    if (i < SS) {
        float a = ah[0], v = vh[0];
        float z = 1.0f + expf(v) / (1.0f + expf(v - a * (float)i));
        g_zt[i] = z * 0.125f * 1.4426950408889634f;
    }
}

// ---------------------------------------------------------------------------
// Split: X -> bf16 hi + fp16 + int8 (val, residual);
//        Wq/Wk -> bf16 hi + int8 (val, residual); Wv -> fp16.
// ---------------------------------------------------------------------------
#define NX8 (MT*FF/8)
#define NW8_1 (HD*FF/8)

__global__ __launch_bounds__(256) void split_kernel(
    const float* __restrict__ X, const float* __restrict__ Wq,
    const float* __restrict__ Wk, const float* __restrict__ Wv)
{
    int i = blockIdx.x * 256 + threadIdx.x;
    if (i < NX8) {
        int off = i;
        float4 v0 = ((const float4*)X)[(size_t)off * 2];
        float4 v1 = ((const float4*)X)[(size_t)off * 2 + 1];
        float f[8] = {v0.x, v0.y, v0.z, v0.w, v1.x, v1.y, v1.z, v1.w};
        __nv_bfloat16 h[8];
        __half p[8];
        int a8[8], r8[8];
#pragma unroll
        for (int k = 0; k < 8; k++) {
            h[k] = __float2bfloat16(f[k]);
            float res = f[k] - __bfloat162float(h[k]);
            a8[k] = q8clamp(f[k] * 31.75f);
            r8[k] = q8clamp(res * 16256.0f);
            p[k] = __float2half_rn(f[k]);
        }
        uint4 H, P;
        H.x = pk2(h[0], h[1]); H.y = pk2(h[2], h[3]);
        H.z = pk2(h[4], h[5]); H.w = pk2(h[6], h[7]);
        P.x = pk2h(p[0], p[1]); P.y = pk2h(p[2], p[3]);
        P.z = pk2h(p[4], p[5]); P.w = pk2h(p[6], p[7]);
        uint2 A, R;
        A.x = pk4b(a8[0], a8[1], a8[2], a8[3]); A.y = pk4b(a8[4], a8[5], a8[6], a8[7]);
        R.x = pk4b(r8[0], r8[1], r8[2], r8[3]); R.y = pk4b(r8[4], r8[5], r8[6], r8[7]);
        ((uint4*)g_Xh)[off] = H;
        ((uint4*)g_X16)[off] = P;
        ((uint2*)g_X8)[off] = A;
        ((uint2*)g_X8r)[off] = R;
    } else {
        int j = i - NX8;
        int m = j >> 15;           // 0=Wq, 1=Wk, 2=Wv
        int off = j & 32767;
        const float* src = (m == 0) ? Wq : ((m == 1) ? Wk : Wv);
        float4 v0 = ((const float4*)src)[(size_t)off * 2];
        float4 v1 = ((const float4*)src)[(size_t)off * 2 + 1];
        float f[8] = {v0.x, v0.y, v0.z, v0.w, v1.x, v1.y, v1.z, v1.w};
        if (m < 2) {
            __nv_bfloat16 h[8];
            int a8[8], r8[8];
#pragma unroll
            for (int k = 0; k < 8; k++) {
                h[k] = __float2bfloat16(f[k]);
                float res = f[k] - __bfloat162float(h[k]);
                a8[k] = q8clamp(f[k] * 512.0f);
                r8[k] = q8clamp(res * 262144.0f);
            }
            uint4 H;
            H.x = pk2(h[0], h[1]); H.y = pk2(h[2], h[3]);
            H.z = pk2(h[4], h[5]); H.w = pk2(h[6], h[7]);
            uint2 A, R;
            A.x = pk4b(a8[0], a8[1], a8[2], a8[3]); A.y = pk4b(a8[4], a8[5], a8[6], a8[7]);
            R.x = pk4b(r8[0], r8[1], r8[2], r8[3]); R.y = pk4b(r8[4], r8[5], r8[6], r8[7]);
            size_t o = (size_t)m * NW8_1 + off;
            ((uint4*)g_Wh)[o] = H;
            ((uint2*)g_W8)[o] = A;
            ((uint2*)g_W8r)[o] = R;
        } else {
            __half p[8];
#pragma unroll
            for (int k = 0; k < 8; k++) p[k] = __float2half_rn(f[k]);
            uint4 P;
            P.x = pk2h(p[0], p[1]); P.y = pk2h(p[2], p[3]);
            P.z = pk2h(p[4], p[5]); P.w = pk2h(p[6], p[7]);
            ((uint4*)g_Wv16)[off] = P;
        }
    }
}

// ---------------------------------------------------------------------------
// Fused QKV projection.
// nb<8: Q/K = Xh·Wh (bf16) + int8 cross (k32, shared s32 acc).
// nb>=8: V via single fp16 MMA.
// ---------------------------------------------------------------------------
#define PROW 144
#define PARR 18432            // 128 rows * 144 (bf16/fp16 arrays)
#define P8ROW 80
#define P8ARR 10240           // 128 rows * 80 (int8 arrays)
#define OX8   PARR
#define OX8R  (PARR + P8ARR)
#define OWH   (PARR + 2*P8ARR)
#define OW8   (2*PARR + 2*P8ARR)
#define OW8R  (2*PARR + 3*P8ARR)
#define PSTG  (2*PARR + 4*P8ARR)   // 77824
#define PROJ_SMEM (2*PSTG)         // 155648

__global__ __launch_bounds__(256) void proj_mma(
    const float* __restrict__ bq, const float* __restrict__ bk,
    const float* __restrict__ bv)
{
    extern __shared__ char sm[];
    const uint32_t sbase = smem_u32(sm);
    const int tid = threadIdx.x;
    const int w = tid >> 5, lane = tid & 31;
    const int gr = lane >> 2, qt = lane & 3;
    const int nb = blockIdx.x;          // 0..11
    const int m0 = blockIdx.y * 128;

    const uint32_t rowoffB = (uint32_t)(((lane & 7) + ((lane >> 4) << 3)) * PROW
                                        + ((lane >> 3) & 1) * 16);
    const uint32_t rowoffA = (uint32_t)(((lane & 7) + (((lane >> 3) & 1) << 3)) * PROW
                                        + (lane >> 4) * 16);
    const uint32_t rowoffB8 = (uint32_t)(((lane & 7) + ((lane >> 4) << 3)) * P8ROW
                                         + ((lane >> 3) & 1) * 16);
    const uint32_t rowoffA8 = (uint32_t)(((lane & 7) + (((lane >> 3) & 1) << 3)) * P8ROW
                                         + (lane >> 4) * 16);

    float acc[16][4];
#pragma unroll
    for (int i = 0; i < 16; i++)
#pragma unroll
        for (int j = 0; j < 4; j++) acc[i][j] = 0.f;

    const uint32_t w16off  = (uint32_t)(w * 16 * PROW);
    const uint32_t w16off8 = (uint32_t)(w * 16 * P8ROW);

    if (nb < 8) {
        // ------------- Q/K path: bf16 hh + int8 cross -------------
        int ia[16][4];
#pragma unroll
        for (int i = 0; i < 16; i++)
#pragma unroll
            for (int j = 0; j < 4; j++) ia[i][j] = 0;

        auto fill = [&](int stg, int k0) {
            char* dstb = sm + stg * PSTG;
#pragma unroll
            for (int ii = 0; ii < 16; ii++) {
                int idx = ii * 256 + tid;    // 0..4095
                uint32_t d;
                if (idx < 1024) {            // Xh: 128 rows x 128B
                    int r = idx >> 3, c = idx & 7;
                    const __nv_bfloat16* src = g_Xh + (size_t)(m0 + r) * FF + k0 + c * 8;
                    d = smem_u32(dstb + r * PROW + c * 16);
                    CP_ASYNC16(d, src);
                } else if (idx < 1536) {     // X8: 128 rows x 64B
                    int j = idx - 1024;
                    int r = j >> 2, c = j & 3;
                    const int8_t* src = g_X8 + (size_t)(m0 + r) * FF + k0 + c * 16;
                    d = smem_u32(dstb + OX8 + r * P8ROW + c * 16);
                    CP_ASYNC16(d, src);
                } else if (idx < 2048) {     // X8r
                    int j = idx - 1536;
                    int r = j >> 2, c = j & 3;
                    const int8_t* src = g_X8r + (size_t)(m0 + r) * FF + k0 + c * 16;
                    d = smem_u32(dstb + OX8R + r * P8ROW + c * 16);
                    CP_ASYNC16(d, src);
                } else if (idx < 3072) {     // Wh: 128 rows x 128B
                    int j = idx - 2048;
                    int r = j >> 3, c = j & 7;
                    const __nv_bfloat16* src = g_Wh + (size_t)(nb * 128 + r) * FF + k0 + c * 8;
                    d = smem_u32(dstb + OWH + r * PROW + c * 16);
                    CP_ASYNC16(d, src);
                } else if (idx < 3584) {     // W8
                    int j = idx - 3072;
                    int r = j >> 2, c = j & 3;
                    const int8_t* src = g_W8 + (size_t)(nb * 128 + r) * FF + k0 + c * 16;
                    d = smem_u32(dstb + OW8 + r * P8ROW + c * 16);
                    CP_ASYNC16(d, src);
                } else {                     // W8r
                    int j = idx - 3584;
                    int r = j >> 2, c = j & 3;
                    const int8_t* src = g_W8r + (size_t)(nb * 128 + r) * FF + k0 + c * 16;
                    d = smem_u32(dstb + OW8R + r * P8ROW + c * 16);
                    CP_ASYNC16(d, src);
                }
            }
            CP_COMMIT();
        };

        fill(0, 0);
        fill(1, 64);

#pragma unroll 1
        for (int ks = 0; ks < 8; ks++) {
            CP_WAIT1();
            __syncthreads();
            const uint32_t B    = sbase + (ks & 1) * PSTG;
            const uint32_t aXh  = B;
            const uint32_t aX8  = B + OX8;
            const uint32_t aX8r = B + OX8R;
            const uint32_t aWh  = B + OWH;
            const uint32_t aW8  = B + OW8;
            const uint32_t aW8r = B + OW8R;
            // ---- bf16 hh ----
#pragma unroll
            for (int kf = 0; kf < 4; kf++) {
                uint32_t xh[4];
                ldsm4(xh, aXh + w16off + kf * 32 + rowoffA);
#pragma unroll
                for (int np = 0; np < 4; np++) {
                    uint32_t wh0[4], wh1[4];
                    ldsm4(wh0, aWh + (2 * np) * (16 * PROW) + kf * 32 + rowoffB);
                    ldsm4(wh1, aWh + (2 * np + 1) * (16 * PROW) + kf * 32 + rowoffB);
                    mma_bf16(acc[4 * np],     xh, &wh0[0]);
                    mma_bf16(acc[4 * np + 1], xh, &wh0[2]);
                    mma_bf16(acc[4 * np + 2], xh, &wh1[0]);
                    mma_bf16(acc[4 * np + 3], xh, &wh1[2]);
                }
            }
            // ---- int8 cross, shared accumulator ----
#pragma unroll
            for (int kc = 0; kc < 2; kc++) {
                uint32_t x8[4], x8r[4];
                ldsm4(x8,  aX8  + w16off8 + kc * 32 + rowoffA8);
                ldsm4(x8r, aX8r + w16off8 + kc * 32 + rowoffA8);
#pragma unroll
                for (int np = 0; np < 4; np++) {
                    uint32_t w8a[4], w8b[4], w8ra[4], w8rb[4];
                    ldsm4(w8ra, aW8r + (2 * np) * (16 * P8ROW) + kc * 32 + rowoffB8);
                    ldsm4(w8rb, aW8r + (2 * np + 1) * (16 * P8ROW) + kc * 32 + rowoffB8);
                    ldsm4(w8a,  aW8  + (2 * np) * (16 * P8ROW) + kc * 32 + rowoffB8);
                    ldsm4(w8b,  aW8  + (2 * np + 1) * (16 * P8ROW) + kc * 32 + rowoffB8);
                    mma_s8(ia[4 * np],     x8, &w8ra[0]);
                    mma_s8(ia[4 * np + 1], x8, &w8ra[2]);
                    mma_s8(ia[4 * np + 2], x8, &w8rb[0]);
                    mma_s8(ia[4 * np + 3], x8, &w8rb[2]);
                    mma_s8(ia[4 * np],     x8r, &w8a[0]);
                    mma_s8(ia[4 * np + 1], x8r, &w8a[2]);
                    mma_s8(ia[4 * np + 2], x8r, &w8b[0]);
                    mma_s8(ia[4 * np + 3], x8r, &w8b[2]);
                }
            }
            __syncthreads();
            if (ks + 2 < 8) fill(ks & 1, (ks + 2) * 64);
        }

        // merge cross terms: DQ = 1/(31.75*262144) = 1/(16256*512)
        const float DQP = 1.0f / 8323072.0f;
#pragma unroll
        for (int i = 0; i < 16; i++)
#pragma unroll
            for (int j = 0; j < 4; j++)
                acc[i][j] = fmaf((float)ia[i][j], DQP, acc[i][j]);
    } else {
        // ------------------- V path: single fp16 MMA -------------------
        auto fillv = [&](int stg, int k0) {
            char* dstb = sm + stg * PSTG;
#pragma unroll
            for (int ii = 0; ii < 8; ii++) {
                int idx = ii * 256 + tid;
                int arr = idx >> 10;            // 0: X16, 1: Wv16
                int r = (idx >> 3) & 127;
                int c = idx & 7;
                const __half* src = (arr == 0)
                    ? g_X16 + (size_t)(m0 + r) * FF + k0 + c * 8
                    : g_Wv16 + (size_t)((nb - 8) * 128 + r) * FF + k0 + c * 8;
                uint32_t d = smem_u32(dstb + arr * PARR + r * PROW + c * 16);
                CP_ASYNC16(d, src);
            }
            CP_COMMIT();
        };

        fillv(0, 0);
        fillv(1, 64);

#pragma unroll 1
        for (int ks = 0; ks < 8; ks++) {
            CP_WAIT1();
            __syncthreads();
            const uint32_t B   = sbase + (ks & 1) * PSTG;
            const uint32_t aX  = B;
            const uint32_t aWv = B + PARR;
#pragma unroll
            for (int kf = 0; kf < 4; kf++) {
                uint32_t x16[4];
                ldsm4(x16, aX + w16off + kf * 32 + rowoffA);
#pragma unroll
                for (int np = 0; np < 4; np++) {
                    uint32_t wv0[4], wv1[4];
                    ldsm4(wv0, aWv + (2 * np) * (16 * PROW) + kf * 32 + rowoffB);
                    ldsm4(wv1, aWv + (2 * np + 1) * (16 * PROW) + kf * 32 + rowoffB);
                    mma_fp16(acc[4 * np],     x16, &wv0[0]);
                    mma_fp16(acc[4 * np + 1], x16, &wv0[2]);
                    mma_fp16(acc[4 * np + 2], x16, &wv1[0]);
                    mma_fp16(acc[4 * np + 3], x16, &wv1[2]);
                }
            }
            __syncthreads();
            if (ks + 2 < 8) fillv(ks & 1, (ks + 2) * 64);
        }
    }

    // ---- epilogue ----
    const int r0 = m0 + w * 16 + gr;
#pragma unroll
    for (int nf = 0; nf < 16; nf++) {
        int ng;
        {
            int np = nf >> 2, j = nf & 3;
            int nfp = 2 * np + (j >> 1);
            int oldnf = 2 * nfp + (j & 1);
            ng = nb * 128 + oldnf * 8 + qt * 2;
        }
        int sel = ng >> 9;
        int within = ng & 511;
        const float* bias = (sel == 0) ? bq : (sel == 1) ? bk : bv;
        float b0 = bias[within], b1 = bias[within + 1];
        int h = within >> 6, d = within & 63;
#pragma unroll
        for (int half = 0; half < 2; half++) {
            int m = r0 + half * 8;
            int bb = m >> 11, s = m & 2047;
            float y0 = acc[nf][half * 2 + 0] + b0;
            float y1 = acc[nf][half * 2 + 1] + b1;
            if (sel < 2) {
                __nv_bfloat16 h0 = __float2bfloat16(y0);
                __nv_bfloat16 h1 = __float2bfloat16(y1);
                float res0 = y0 - __bfloat162float(h0);
                float res1 = y1 - __bfloat162float(h1);
                int i0 = q8clamp(y0 * 31.75f);
                int i1 = q8clamp(y1 * 31.75f);
                int j0 = q8clamp(res0 * 16256.0f);
                int j1 = q8clamp(res1 * 16256.0f);
                __nv_bfloat16* dh = (sel == 0) ? g_Qh : g_Kh;
                int8_t* d8  = (sel == 0) ? g_Q8  : g_K8;
                int8_t* d8r = (sel == 0) ? g_Q8r : g_K8r;
                size_t a = (((size_t)(bb * HH + h)) * SS + s) * DD + d;
                *(uint32_t*)&dh[a] = pk2(h0, h1);
                *(unsigned short*)&d8[a]  = (unsigned short)((i0 & 0xff) | ((i1 & 0xff) << 8));
                *(unsigned short*)&d8r[a] = (unsigned short)((j0 & 0xff) | ((j1 & 0xff) << 8));
            } else {
                size_t a0 = (((size_t)(bb * HH + h)) * DD + d) * SS + s;
                g_Vth[a0]      = __float2half_rn(y0);
                g_Vth[a0 + SS] = __float2half_rn(y1);
            }
        }
    }
}

// ---------------------------------------------------------------------------
// Flash attention: S = Qh·Kh (bf16) + int8 cross (k32), PV = fp16.
// 128 threads (4 warps, 64 q-rows), 32-key tiles, 2-stage ring, 4 CTAs/SM.
// ---------------------------------------------------------------------------
#define NT 64
#define KROW 144
#define K8ROW 80
#define VROW 80
#define KARR (32*KROW)
#define K8ARR (32*K8ROW)
#define VARR (64*VROW)
#define OK8  KARR
#define OK8R (KARR + K8ARR)
#define OV   (KARR + 2*K8ARR)
#define ASTG (KARR + 2*K8ARR + VARR)
#define AZT  (2*ASTG)
#define ATTN_SMEM (AZT + SS*4)

__global__ __launch_bounds__(128, 4) void attn_mma(float* __restrict__ out)
{
    extern __shared__ char sm[];
    const uint32_t sbase = smem_u32(sm);
    float* zts = (float*)(sm + AZT);
    const int tid = threadIdx.x;
    const int w = tid >> 5, lane = tid & 31;
    const int gr = lane >> 2, qt = lane & 3;
    const int bh = blockIdx.y;
    const int q0 = blockIdx.x * 64;

    const uint32_t rowK = (uint32_t)(((lane & 7) + ((lane >> 4) << 3)) * KROW
                                     + ((lane >> 3) & 1) * 16);
    const uint32_t rowI8 = (uint32_t)(((lane & 7) + ((lane >> 4) << 3)) * K8ROW
                                      + ((lane >> 3) & 1) * 16);
    const uint32_t rowV = (uint32_t)(((lane & 7) + ((lane >> 4) << 3)) * VROW
                                     + ((lane >> 3) & 1) * 16);

    for (int i = tid; i < SS; i += 128) zts[i] = g_zt[i];

    const int r0 = q0 + w * 16 + gr;
    const __nv_bfloat16* Qh = g_Qh + (size_t)bh * SS * DD;
    uint32_t qah[4][4];
#pragma unroll
    for (int kf = 0; kf < 4; kf++) {
        int col = kf * 16 + qt * 2;
        qah[kf][0] = *(const uint32_t*)(Qh + (size_t)r0 * 64 + col);
        qah[kf][1] = *(const uint32_t*)(Qh + (size_t)(r0 + 8) * 64 + col);
        qah[kf][2] = *(const uint32_t*)(Qh + (size_t)r0 * 64 + col + 8);
        qah[kf][3] = *(const uint32_t*)(Qh + (size_t)(r0 + 8) * 64 + col + 8);
    }
    const int8_t* Q8  = g_Q8  + (size_t)bh * SS * DD;
    const int8_t* Q8r = g_Q8r + (size_t)bh * SS * DD;
    uint32_t q8[2][4], q8r[2][4];
#pragma unroll
    for (int kc = 0; kc < 2; kc++) {
        int col = kc * 32 + qt * 4;
        q8[kc][0]  = *(const uint32_t*)(Q8  + (size_t)r0 * 64 + col);
        q8[kc][1]  = *(const uint32_t*)(Q8  + (size_t)(r0 + 8) * 64 + col);
        q8[kc][2]  = *(const uint32_t*)(Q8  + (size_t)r0 * 64 + col + 16);
        q8[kc][3]  = *(const uint32_t*)(Q8  + (size_t)(r0 + 8) * 64 + col + 16);
        q8r[kc][0] = *(const uint32_t*)(Q8r + (size_t)r0 * 64 + col);
        q8r[kc][1] = *(const uint32_t*)(Q8r + (size_t)(r0 + 8) * 64 + col);
        q8r[kc][2] = *(const uint32_t*)(Q8r + (size_t)r0 * 64 + col + 16);
        q8r[kc][3] = *(const uint32_t*)(Q8r + (size_t)(r0 + 8) * 64 + col + 16);
    }

    auto fill = [&](int slot, int k0) {
        char* dstb = sm + slot * ASTG;
#pragma unroll
        for (int ii = 0; ii < 6; ii++) {
            int idx = ii * 128 + tid;
            uint32_t d;
            if (idx < 256) {
                int r = idx >> 3, c = idx & 7;
                const __nv_bfloat16* src =
                    g_Kh + ((size_t)bh * SS + k0 + r) * 64 + c * 8;
                d = smem_u32(dstb + r * KROW + c * 16);
                CP_ASYNC16(d, src);
            } else if (idx < 384) {
                int j = idx - 256;
                int r = j >> 2, c = j & 3;
                const int8_t* src = g_K8 + ((size_t)bh * SS + k0 + r) * 64 + c * 16;
                d = smem_u32(dstb + OK8 + r * K8ROW + c * 16);
                CP_ASYNC16(d, src);
            } else if (idx < 512) {
                int j = idx - 384;
                int r = j >> 2, c = j & 3;
                const int8_t* src = g_K8r + ((size_t)bh * SS + k0 + r) * 64 + c * 16;
                d = smem_u32(dstb + OK8R + r * K8ROW + c * 16);
                CP_ASYNC16(d, src);
            } else {
                int j = idx - 512;
                int r = j >> 2, c = j & 3;
                const __half* src = g_Vth + ((size_t)bh * DD + r) * SS + k0 + c * 8;
                d = smem_u32(dstb + OV + r * VROW + c * 16);
                CP_ASYNC16(d, src);
            }
        }
        CP_COMMIT();
    };

    fill(0, 0);
    fill(1, 32);

    float O[8][4];
#pragma unroll
    for (int i = 0; i < 8; i++)
#pragma unroll
        for (int j = 0; j < 4; j++) O[i][j] = 0.f;
    float m0r = -1e30f, m1r = -1e30f, l0r = 0.f, l1r = 0.f;

    const float DQ = 4.0f / (127.0f * 127.0f * 128.0f);

#pragma unroll 1
    for (int kt = 0; kt < NT; kt++) {
        CP_WAIT1();
        __syncthreads();
        const uint32_t B    = sbase + (kt & 1) * ASTG;
        const uint32_t aKh  = B;
        const uint32_t aK8  = B + OK8;
        const uint32_t aK8r = B + OK8R;
        const uint32_t aVth = B + OV;
        const int k0 = kt * 32;

        float S[4][4];
#pragma unroll
        for (int i = 0; i < 4; i++)
#pragma unroll
            for (int j = 0; j < 4; j++) S[i][j] = 0.f;

#pragma unroll
        for (int kf = 0; kf < 4; kf++) {
            uint32_t rh0[4], rh1[4];
            ldsm4(rh0, aKh + kf * 32 + rowK);
            ldsm4(rh1, aKh + 16 * KROW + kf * 32 + rowK);
            mma_bf16(S[0], qah[kf], &rh0[0]); mma_bf16(S[1], qah[kf], &rh0[2]);
            mma_bf16(S[2], qah[kf], &rh1[0]); mma_bf16(S[3], qah[kf], &rh1[2]);
        }

        int ia[4][4];
#pragma unroll
        for (int i = 0; i < 4; i++)
#pragma unroll
            for (int j = 0; j < 4; j++) ia[i][j] = 0;

#pragma unroll
        for (int kc = 0; kc < 2; kc++) {
            uint32_t kh8a[4], kh8b[4], kr8a[4], kr8b[4];
            ldsm4(kr8a, aK8r + kc * 32 + rowI8);
            ldsm4(kr8b, aK8r + 16 * K8ROW + kc * 32 + rowI8);
            ldsm4(kh8a, aK8 + kc * 32 + rowI8);
            ldsm4(kh8b, aK8 + 16 * K8ROW + kc * 32 + rowI8);
            mma_s8(ia[0], q8[kc], &kr8a[0]); mma_s8(ia[1], q8[kc], &kr8a[2]);
            mma_s8(ia[2], q8[kc], &kr8b[0]); mma_s8(ia[3], q8[kc], &kr8b[2]);
            mma_s8(ia[0], q8r[kc], &kh8a[0]); mma_s8(ia[1], q8r[kc], &kh8a[2]);
            mma_s8(ia[2], q8r[kc], &kh8b[0]); mma_s8(ia[3], q8r[kc], &kh8b[2]);
        }
#pragma unroll
        for (int i = 0; i < 4; i++)
#pragma unroll
            for (int j = 0; j < 4; j++)
                S[i][j] = fmaf((float)ia[i][j], DQ, S[i][j]);

        float mt0 = -1e30f, mt1 = -1e30f;
#pragma unroll
        for (int nf = 0; nf < 4; nf++) {
            int c0 = k0 + nf * 8 + qt * 2;
            S[nf][0] *= zts[abs(r0 - c0)];
            S[nf][1] *= zts[abs(r0 - c0 - 1)];
            S[nf][2] *= zts[abs(r0 + 8 - c0)];
            S[nf][3] *= zts[abs(r0 + 8 - c0 - 1)];
            mt0 = fmaxf(mt0, fmaxf(S[nf][0], S[nf][1]));
            mt1 = fmaxf(mt1, fmaxf(S[nf][2], S[nf][3]));
        }
        mt0 = fmaxf(mt0, __shfl_xor_sync(0xffffffffu, mt0, 1));
        mt0 = fmaxf(mt0, __shfl_xor_sync(0xffffffffu, mt0, 2));
        mt1 = fmaxf(mt1, __shfl_xor_sync(0xffffffffu, mt1, 1));
        mt1 = fmaxf(mt1, __shfl_xor_sync(0xffffffffu, mt1, 2));
        bool changed = (mt0 > m0r) || (mt1 > m1r);
        if (__any_sync(0xffffffffu, changed)) {
            float mn0 = fmaxf(m0r, mt0), mn1 = fmaxf(m1r, mt1);
            float a0 = ex2f(m0r - mn0), a1 = ex2f(m1r - mn1);
            m0r = mn0; m1r = mn1;
            l0r *= a0; l1r *= a1;
#pragma unroll
            for (int nf = 0; nf < 8; nf++) {
                O[nf][0] *= a0; O[nf][1] *= a0;
                O[nf][2] *= a1; O[nf][3] *= a1;
            }
        }

        float s0 = 0.f, s1 = 0.f;
        uint32_t ph[2][4];
#pragma unroll
        for (int nf = 0; nf < 4; nf++) {
            float e0 = ex2f(S[nf][0] - m0r);
            float e1 = ex2f(S[nf][1] - m0r);
            float e2 = ex2f(S[nf][2] - m1r);
            float e3 = ex2f(S[nf][3] - m1r);
            s0 += e0 + e1; s1 += e2 + e3;
            uint32_t p01 = cvt_f16x2(e1, e0);
            uint32_t p23 = cvt_f16x2(e3, e2);
            int kf = nf >> 1;
            if ((nf & 1) == 0) { ph[kf][0] = p01; ph[kf][1] = p23; }
            else               { ph[kf][2] = p01; ph[kf][3] = p23; }
        }
        l0r += s0;
        l1r += s1;

#pragma unroll
        for (int kf = 0; kf < 2; kf++) {
#pragma unroll
            for (int g = 0; g < 2; g++) {
                uint32_t va0[4], va1[4];
                ldsm4(va0, aVth + (2 * g) * (16 * VROW) + kf * 32 + rowV);
                ldsm4(va1, aVth + (2 * g + 1) * (16 * VROW) + kf * 32 + rowV);
                float* o0 = O[4 * g];
                float* o1 = O[4 * g + 1];
                float* o2 = O[4 * g + 2];
                float* o3 = O[4 * g + 3];
                mma_fp16(o0, ph[kf], &va0[0]); mma_fp16(o1, ph[kf], &va0[2]);
                mma_fp16(o2, ph[kf], &va1[0]); mma_fp16(o3, ph[kf], &va1[2]);
            }
        }

        __syncthreads();
        if (kt + 2 < NT) fill(kt & 1, (kt + 2) * 32);
    }

    l0r += __shfl_xor_sync(0xffffffffu, l0r, 1);
    l0r += __shfl_xor_sync(0xffffffffu, l0r, 2);
    l1r += __shfl_xor_sync(0xffffffffu, l1r, 1);
    l1r += __shfl_xor_sync(0xffffffffu, l1r, 2);
    float inv0 = 1.0f / l0r, inv1 = 1.0f / l1r;
    int b = bh >> 3, h = bh & 7;
#pragma unroll
    for (int nf = 0; nf < 8; nf++) {
        int g = nf >> 2, j = nf & 3;
        int oldnf = 2 * (2 * g + (j >> 1)) + (j & 1);
        int d = oldnf * 8 + qt * 2;
        float2 o0 = make_float2(O[nf][0] * inv0, O[nf][1] * inv0);
        float2 o1 = make_float2(O[nf][2] * inv1, O[nf][3] * inv1);
        *(float2*)&out[((size_t)(b * SS) + r0) * HD + h * 64 + d]       = o0;
        *(float2*)&out[((size_t)(b * SS) + r0 + 8) * HD + h * 64 + d]   = o1;
    }
}

// ---------------------------------------------------------------------------
extern "C" void kernel_launch(void* const* d_in, const int* in_sizes, int n_in,
                              void* d_out, int out_size)
{
    const float* x  = (const float*)d_in[0];
    const float* Wq = (const float*)d_in[1];
    const float* bq = (const float*)d_in[2];
    const float* Wk = (const float*)d_in[3];
    const float* bk = (const float*)d_in[4];
    const float* Wv = (const float*)d_in[5];
    const float* bv = (const float*)d_in[6];
    const float* ah = (const float*)d_in[7];
    const float* vh = (const float*)d_in[8];
    float* out = (float*)d_out;

    zhat_kernel<<<SS / 256, 256>>>(ah, vh);
    split_kernel<<<(NX8 + 3 * NW8_1) / 256, 256>>>(x, Wq, Wk, Wv);

    cudaFuncSetAttribute(proj_mma,
                         cudaFuncAttributeMaxDynamicSharedMemorySize, PROJ_SMEM);
    proj_mma<<<dim3(12, 64), 256, PROJ_SMEM>>>(bq, bk, bv);

    cudaFuncSetAttribute(attn_mma,
                         cudaFuncAttributeMaxDynamicSharedMemorySize, ATTN_SMEM);
    attn_mma<<<dim3(SS / 64, BB * HH), 128, ATTN_SMEM>>>(out);
}